// round 10
// baseline (speedup 1.0000x reference)
#include <cuda_runtime.h>
#include <math.h>

#define HID 64
#define NMAX 8192
#define EMAX 131072
#define NBLK 144
#define NTHR 512
#define NSTEP 10

// ---------------- device scratch (no allocation allowed) ----------------
__device__ float  g_Cij[EMAX];
__device__ float  g_jc[EMAX];
__device__ float2 g_em2[EMAX];       // final messages (dumped post-loop)
__device__ float  g_f1[NMAX];
__device__ float  g_f2[NMAX];
__device__ float  g_Ci[NMAX];
__device__ float2 g_x2[NMAX];        // x = bx + nm/dom (the per-step global)
__device__ float2 g_lr2[NMAX];       // log-readout (for P6)
__device__ float  g_npart[NBLK];
__device__ float  g_epart[NBLK];
__device__ unsigned g_count;         // returns to 0 after every barrier
__device__ unsigned g_sense;         // lsense derived at entry -> parity-safe
__device__ unsigned g_done;          // last-block finalize counter (reset per launch)

// Fence-light sense-reversal barrier. PURE SPIN waiters (no __nanosleep):
// HW sleep quantum made release-detection latency ~µs-scale; a bare
// ld.acquire.gpu poll detects within one L2 round trip (~250 cyc) and only
// one thread per block spins. Cross-block data after a barrier is read via
// __ldcg (L2 = coherence point).
__device__ __forceinline__ void grid_barrier(unsigned& lsense) {
    __syncthreads();
    if (threadIdx.x == 0) {
        unsigned s = lsense ^ 1u;
        lsense = s;
        unsigned prev;
        asm volatile("atom.release.gpu.add.u32 %0, [%1], %2;"
                     : "=r"(prev) : "l"(&g_count), "r"(1u) : "memory");
        if (prev == gridDim.x - 1u) {
            g_count = 0u;   // ordered before the release store below
            asm volatile("st.release.gpu.u32 [%0], %1;"
                         :: "l"(&g_sense), "r"(s) : "memory");
        } else {
            unsigned v;
            do {
                asm volatile("ld.acquire.gpu.u32 %0, [%1];"
                             : "=r"(v) : "l"(&g_sense) : "memory");
            } while (v != s);
        }
    }
    __syncthreads();
}

__global__ __launch_bounds__(NTHR, 1)
void k_fused(const float* __restrict__ J, const float* __restrict__ bias,
             const float* __restrict__ gat_W, const float* __restrict__ gat_a,
             const float* __restrict__ W1, const float* __restrict__ b1,
             const float* __restrict__ W2, const float* __restrict__ b2,
             const float* __restrict__ W3, const float* __restrict__ b3,
             const int* __restrict__ row, const int* __restrict__ col,
             const int* __restrict__ rev, const int* __restrict__ ru,
             const int* __restrict__ cu, const int* __restrict__ u2e,
             int N, int E, int Eu,
             float* __restrict__ out_readout, float* __restrict__ out_pw,
             float* __restrict__ out_scal, float* __restrict__ out_Ci,
             float* __restrict__ out_cij, float* __restrict__ out_dom)
{
    __shared__ float sW2[HID * HID];
    __shared__ float sh1[8][HID];
    __shared__ float sr[8][2][3];
    __shared__ float sred[NTHR];
    __shared__ float sJv[NTHR];          // block-local edge J values

    const int tid = threadIdx.x;
    const int b = blockIdx.x;
    const int gsize = NBLK * NTHR;
    const int DEG = E / N;               // uniform degree (16)
    unsigned lsense;
    asm volatile("ld.acquire.gpu.u32 %0, [%1];" : "=r"(lsense) : "l"(&g_sense));

    const int npb = (N + NBLK - 1) / NBLK;   // 29 for N=4096, NBLK=144
    const int n0 = b * npb;
    const int n1 = min(N, n0 + npb);
    const bool live = (n0 < n1);             // tail blocks may own no nodes
    const int es = n0 * DEG;

    if (live) {
        // ===== P1: own-chunk Jv gather into SMEM (block-local edges) =========
        for (int e = es + tid; e < n1 * DEG; e += NTHR) {
            int r = e / DEG;
            sJv[e - es] = J[(long long)r * N + col[e]];
        }
        __syncthreads();

        // ===== P2: node features + GAT f1/f2 + Ci MLP ========================
        for (int i = tid; i < HID * HID; i += NTHR) sW2[i] = W2[i];
        int u = tid & 63;
        int nl8 = tid >> 6;
        // hoist per-unit weights into registers (reused across all passes)
        float wg0 = gat_W[u],           wg1 = gat_W[HID + u];
        float wg2 = gat_W[2 * HID + u], wg3 = gat_W[3 * HID + u];
        float a1u = gat_a[u],           a2u = gat_a[HID + u];
        float w10 = W1[u],              w11 = W1[HID + u];
        float w12 = W1[2 * HID + u],    w13 = W1[3 * HID + u];
        float b1u = b1[u], b2u = b2[u], w3u = W3[u], b3s = b3[0];
        const int npass = (npb + 7) / 8;
        for (int p = 0; p < npass; p++) {
            int node = n0 + p * 8 + nl8;
            int nc = node < n1 ? node : n1 - 1;
            float bb = bias[nc];
            int s0 = (nc - n0) * DEG;
            float Jsum = 0.0f;
            for (int k2 = 0; k2 < DEG; k2++) Jsum += sJv[s0 + k2];
            float ft0 = -bb, ft1 = bb, ft2 = (float)DEG, ft3 = Jsum;
            float wh = ft0 * wg0 + ft1 * wg1 + ft2 * wg2 + ft3 * wg3;
            float c1 = wh * a1u;
            float c2 = wh * a2u;
            float h1 = b1u + ft0 * w10 + ft1 * w11 + ft2 * w12 + ft3 * w13;
            h1 = fmaxf(h1, 0.0f);
            sh1[nl8][u] = h1;
            #pragma unroll
            for (int off = 16; off > 0; off >>= 1) {
                c1 += __shfl_down_sync(0xffffffffu, c1, off);
                c2 += __shfl_down_sync(0xffffffffu, c2, off);
            }
            int half = u >> 5;
            if ((u & 31) == 0) { sr[nl8][half][0] = c1; sr[nl8][half][1] = c2; }
            __syncthreads();
            float h2 = b2u;
            #pragma unroll 8
            for (int k2 = 0; k2 < HID; k2++) h2 += sh1[nl8][k2] * sW2[k2 * HID + u];
            h2 = fmaxf(h2, 0.0f);
            float cp = h2 * w3u;
            #pragma unroll
            for (int off = 16; off > 0; off >>= 1)
                cp += __shfl_down_sync(0xffffffffu, cp, off);
            if ((u & 31) == 0) sr[nl8][half][2] = cp;
            __syncthreads();
            if (node < n1 && u == 0) {
                g_f1[node] = sr[nl8][0][0] + sr[nl8][1][0];
                g_f2[node] = sr[nl8][0][1] + sr[nl8][1][1];
                float Ci = sr[nl8][0][2] + sr[nl8][1][2] + b3s;
                g_Ci[node] = Ci;
                out_Ci[node] = Ci;
            }
            __syncthreads();
        }
    }
    grid_barrier(lsense);                                   // B-A (f1/f2 global)

    // ===== P3: per-thread edge/node constants + x0 ==========================
    const int jl = tid >> 4;
    const int k = tid & 15;
    const int jn = n0 + jl;
    const bool nv = live && (jl < npb) && (jn < n1);
    const bool ev = nv && (k < DEG);
    int e_out = 0, i_nb = 0;
    float jc = 0.0f, C = 0.0f;
    if (ev) {
        e_out = jn * DEG + k;                 // directed edge (jn -> i_nb)
        i_nb = col[e_out];
        float f1j = __ldcg(&g_f1[jn]);
        float f2j = __ldcg(&g_f2[jn]);
        float f1i = __ldcg(&g_f1[i_nb]);
        float f2i = __ldcg(&g_f2[i_nb]);
        float a = f1j + f2i;
        float bb = f1i + f2j;
        a = (a >= 0.0f) ? a : 0.2f * a;       // leaky_relu 0.2
        bb = (bb >= 0.0f) ? bb : 0.2f * bb;
        C = 0.5f * (__expf(a) + __expf(bb));  // symmetric both directions
        jc = sJv[e_out - es] / C;
        g_Cij[e_out] = C;
        g_jc[e_out] = jc;
    }
    float csum = ev ? C : 0.0f;
    #pragma unroll
    for (int off = 8; off > 0; off >>= 1)
        csum += __shfl_xor_sync(0xffffffffu, csum, off);
    float rdom = 1.0f, bx0 = 0.0f, bx1 = 0.0f, x0 = 0.0f, x1 = 0.0f;
    if (nv) {
        float d = g_Ci[jn] + csum;
        float sgn = (d > 0.0f) ? 1.0f : ((d < 0.0f) ? -1.0f : 0.0f);
        float dom = sgn * fmaxf(fabsf(d), 0.1f);
        rdom = 1.0f / dom;
        float bs = bias[jn] * rdom;
        bx0 = -bs; bx1 = bs;
        x0 = bx0; x1 = bx1;                   // em0 = 0 -> nm = 0
        if (k == 0) {
            g_x2[jn] = make_float2(x0, x1);
            out_dom[jn] = dom;
        }
    }
    float ei0 = 0.0f, ei1 = 0.0f;             // em on in-edge  (i_nb -> jn)
    float eo0 = 0.0f, eo1 = 0.0f;             // em on out-edge (jn -> i_nb)
    grid_barrier(lsense);                                   // B-B (x0 global)

    // ===== P4: BP loop — pure log-domain, registers only ====================
    for (int t = 0; t < NSTEP; t++) {
        float ni0 = 0.0f, ni1 = 0.0f;
        if (ev) {
            float2 xi = __ldcg(&g_x2[i_nb]); // only remote data per step
            // out-message (jn->i): log-max form
            float d0 = x0 - ei0, d1 = x1 - ei1;
            float lt0 = fmaxf(jc + d0, d1 - jc);
            float lt1 = fmaxf(d0 - jc, jc + d1);
            float lse = fmaxf(lt0, lt1)
                      + __logf(1.0f + __expf(-fabsf(lt0 - lt1)));
            float no0 = C * (lt0 - lse);
            float no1 = C * (lt1 - lse);
            // in-message (i->jn)
            float c0 = xi.x - eo0, c1 = xi.y - eo1;
            float ls0 = fmaxf(jc + c0, c1 - jc);
            float ls1 = fmaxf(c0 - jc, jc + c1);
            float lsi = fmaxf(ls0, ls1)
                      + __logf(1.0f + __expf(-fabsf(ls0 - ls1)));
            ni0 = C * (ls0 - lsi);
            ni1 = C * (ls1 - lsi);
            eo0 = no0; eo1 = no1;
            ei0 = ni0; ei1 = ni1;
        }
        float m0 = ni0, m1 = ni1;
        #pragma unroll
        for (int off = 8; off > 0; off >>= 1) {
            m0 += __shfl_xor_sync(0xffffffffu, m0, off);
            m1 += __shfl_xor_sync(0xffffffffu, m1, off);
        }
        if (nv) {
            x0 = bx0 + m0 * rdom;
            x1 = bx1 + m1 * rdom;
            if (k == 0 && t != NSTEP - 1) g_x2[jn] = make_float2(x0, x1);
        }
        if (t != NSTEP - 1) grid_barrier(lsense);           // 9 in-loop barriers
    }

    // ===== P5: dump messages + readout (+log) + node entropy ================
    if (ev) g_em2[e_out] = make_float2(eo0, eo1);
    float pnode = 0.0f;
    if (nv && k == 0) {
        float lse = fmaxf(x0, x1) + __logf(1.0f + __expf(-fabsf(x0 - x1)));
        float lr0 = x0 - lse, lr1 = x1 - lse;
        float r0 = __expf(lr0), r1 = __expf(lr1);
        out_readout[2 * jn] = r0;
        out_readout[2 * jn + 1] = r1;
        g_lr2[jn] = make_float2(lr0, lr1);
        float nH = -(r0 * lr0 + r1 * lr1);
        pnode = g_Ci[jn] * nH;
    }
    if (tid < 32) sred[tid] = 0.0f;
    __syncthreads();
    if (nv && k == 0 && jl < 32) sred[jl] = pnode;
    __syncthreads();
    if (tid == 0) {
        float s = 0.0f;
        for (int i2 = 0; i2 < npb && i2 < 32; i2++) s += sred[i2];
        g_npart[b] = s;
    }
    grid_barrier(lsense);                                   // B-L (em/lr global)

    // ===== P6: pairwise readout + edge entropy (log-domain) =================
    float pedge = 0.0f;
    for (int uu = b * NTHR + tid; uu < Eu; uu += gsize) {
        int e = u2e[uu];
        int er = rev[e];
        int ci = cu[uu], rj = ru[uu];
        float Js = __ldcg(&g_jc[e]);
        float Cu = __ldcg(&g_Cij[e]);
        float2 eme = __ldcg(&g_em2[e]);
        float2 emr = __ldcg(&g_em2[er]);
        float2 li = __ldcg(&g_lr2[ci]);
        float2 lj = __ldcg(&g_lr2[rj]);
        float lti0 = li.x - eme.x, lti1 = li.y - eme.y;
        float ltj0 = lj.x - emr.x, ltj1 = lj.y - emr.y;
        float lp00 =  Js + lti0 + ltj0;
        float lp01 = -Js + lti1 + ltj0;
        float lp10 = -Js + lti0 + ltj1;
        float lp11 =  Js + lti1 + ltj1;
        float m = fmaxf(fmaxf(lp00, lp01), fmaxf(lp10, lp11));
        float e00 = __expf(lp00 - m), e01 = __expf(lp01 - m);
        float e10 = __expf(lp10 - m), e11 = __expf(lp11 - m);
        float S = e00 + e01 + e10 + e11;
        float invS = __frcp_rn(S);
        float lS = __logf(S);
        float q00 = e00 * invS, q01 = e01 * invS;
        float q10 = e10 * invS, q11 = e11 * invS;
        out_pw[4 * uu]     = q00;
        out_pw[4 * uu + 1] = q01;
        out_pw[4 * uu + 2] = q10;
        out_pw[4 * uu + 3] = q11;
        out_cij[uu] = Cu;
        float eH = -(q00 * (lp00 - m - lS) + q01 * (lp01 - m - lS)
                   + q10 * (lp10 - m - lS) + q11 * (lp11 - m - lS));
        pedge += Cu * eH;
    }
    sred[tid] = pedge;
    __syncthreads();
    #pragma unroll
    for (int off = NTHR / 2; off > 0; off >>= 1) {
        if (tid < off) sred[tid] += sred[tid + off];
        __syncthreads();
    }

    // ===== P7: last-arriving block finalizes scalars ========================
    if (tid == 0) {
        g_epart[b] = sred[0];
        unsigned prev;
        asm volatile("atom.acq_rel.gpu.add.u32 %0, [%1], %2;"
                     : "=r"(prev) : "l"(&g_done), "r"(1u) : "memory");
        if (prev == (unsigned)(NBLK - 1)) {
            float ne = 0.0f, ed = 0.0f;
            for (int i2 = 0; i2 < NBLK; i2++) ne += __ldcg(&g_npart[i2]);
            for (int i2 = 0; i2 < NBLK; i2++) ed += __ldcg(&g_epart[i2]);
            out_scal[0] = ne + ed;
            out_scal[1] = ne;
            out_scal[2] = ed;
            g_done = 0u;     // reset for next graph replay
        }
    }
}

// ---------------- launcher ---------------------------------------------------
extern "C" void kernel_launch(void* const* d_in, const int* in_sizes, int n_in,
                              void* d_out, int out_size) {
    const float* J     = (const float*)d_in[0];
    const float* bias  = (const float*)d_in[1];
    const float* gat_W = (const float*)d_in[2];
    const float* gat_a = (const float*)d_in[3];
    const float* W1    = (const float*)d_in[4];
    const float* b1    = (const float*)d_in[5];
    const float* W2    = (const float*)d_in[6];
    const float* b2    = (const float*)d_in[7];
    const float* W3    = (const float*)d_in[8];
    const float* b3    = (const float*)d_in[9];
    const int*   row   = (const int*)d_in[10];
    const int*   col   = (const int*)d_in[11];
    const int*   rev   = (const int*)d_in[12];
    const int*   ru    = (const int*)d_in[13];
    const int*   cu    = (const int*)d_in[14];
    const int*   u2e   = (const int*)d_in[15];

    int N  = in_sizes[1];
    int E  = in_sizes[10];
    int Eu = in_sizes[13];

    float* out = (float*)d_out;
    float* out_readout = out;                    // [N,2]
    float* out_pw      = out + 2 * N;            // [Eu,4]
    float* out_scal    = out + 2 * N + 4 * Eu;   // 3 scalars
    float* out_Ci      = out_scal + 3;           // [N]
    float* out_cij     = out_Ci + N;             // [Eu]
    float* out_dom     = out_cij + Eu;           // [N]

    k_fused<<<NBLK, NTHR>>>(J, bias, gat_W, gat_a, W1, b1, W2, b2, W3, b3,
                            row, col, rev, ru, cu, u2e, N, E, Eu,
                            out_readout, out_pw, out_scal, out_Ci, out_cij,
                            out_dom);
}

// round 13
// speedup vs baseline: 1.2732x; 1.2732x over previous
#include <cuda_runtime.h>
#include <math.h>

#define HID 64
#define NMAX 8192
#define EMAX 131072
#define NBLK 144
#define NTHR 512
#define NSTEP 10

// ---------------- device scratch (no allocation allowed) ----------------
__device__ float  g_Jv[EMAX];
__device__ float  g_Cij[EMAX];
__device__ float  g_jc[EMAX];
__device__ float2 g_em2[EMAX];       // final messages
__device__ float  g_f1[NMAX];
__device__ float  g_f2[NMAX];
__device__ float  g_Ci[NMAX];
__device__ float2 g_x2[NMAX];        // x = bx + nm/dom (the per-step global)
__device__ float2 g_lr2[NMAX];       // log-readout
__device__ float  g_npart[NBLK];
__device__ float  g_epart[NBLK];
__device__ __align__(128) unsigned g_count;  // monotonic barrier counter
__device__ __align__(128) unsigned g_done;   // K3 finalize counter

// Monotonic-counter grid barrier (K2 only). Arrival = red.release (no
// return, no RTT on critical path). Waiters poll relaxed, then one acquire
// load for ordering. No reset inside the kernel -> no ABA/reset races;
// K1 zeroes g_count each launch (quiescent: K1 finishes before K2 starts).
__device__ __forceinline__ void gbar(unsigned& tgt) {
    __syncthreads();
    if (threadIdx.x == 0) {
        asm volatile("red.release.gpu.add.u32 [%0], %1;"
                     :: "l"(&g_count), "r"(1u) : "memory");
        unsigned v;
        do {
            asm volatile("ld.relaxed.gpu.u32 %0, [%1];"
                         : "=r"(v) : "l"(&g_count) : "memory");
        } while (v < tgt);
        asm volatile("ld.acquire.gpu.u32 %0, [%1];"   // ordering fence-load
                     : "=r"(v) : "l"(&g_count) : "memory");
    }
    tgt += NBLK;
    __syncthreads();
}

// ============ K1: J gather + node features + GAT f1/f2 + Ci MLP ============
__global__ __launch_bounds__(NTHR, 1)
void k_feat(const float* __restrict__ J, const float* __restrict__ bias,
            const float* __restrict__ gat_W, const float* __restrict__ gat_a,
            const float* __restrict__ W1, const float* __restrict__ b1,
            const float* __restrict__ W2, const float* __restrict__ b2,
            const float* __restrict__ W3, const float* __restrict__ b3,
            const int* __restrict__ col, int N, int E,
            float* __restrict__ out_Ci)
{
    __shared__ float sW2[HID * HID];
    __shared__ float sh1[8][HID];
    __shared__ float sr[8][2][3];
    __shared__ float sJv[NTHR];

    const int tid = threadIdx.x;
    const int b = blockIdx.x;
    const int DEG = E / N;
    if (b == 0 && tid == 0) { g_count = 0u; g_done = 0u; }  // quiescent reset

    const int npb = (N + NBLK - 1) / NBLK;
    const int n0 = b * npb;
    const int n1 = min(N, n0 + npb);
    if (n0 >= n1) return;
    const int es = n0 * DEG;

    for (int e = es + tid; e < n1 * DEG; e += NTHR) {
        int r = e / DEG;
        float v = J[(long long)r * N + col[e]];
        sJv[e - es] = v;
        g_Jv[e] = v;
    }
    for (int i = tid; i < HID * HID; i += NTHR) sW2[i] = W2[i];
    __syncthreads();

    int u = tid & 63;
    int nl8 = tid >> 6;
    float wg0 = gat_W[u],           wg1 = gat_W[HID + u];
    float wg2 = gat_W[2 * HID + u], wg3 = gat_W[3 * HID + u];
    float a1u = gat_a[u],           a2u = gat_a[HID + u];
    float w10 = W1[u],              w11 = W1[HID + u];
    float w12 = W1[2 * HID + u],    w13 = W1[3 * HID + u];
    float b1u = b1[u], b2u = b2[u], w3u = W3[u], b3s = b3[0];
    const int npass = (npb + 7) / 8;
    for (int p = 0; p < npass; p++) {
        int node = n0 + p * 8 + nl8;
        int nc = node < n1 ? node : n1 - 1;
        float bb = bias[nc];
        int s0 = (nc - n0) * DEG;
        float Jsum = 0.0f;
        for (int k2 = 0; k2 < DEG; k2++) Jsum += sJv[s0 + k2];
        float ft0 = -bb, ft1 = bb, ft2 = (float)DEG, ft3 = Jsum;
        float wh = ft0 * wg0 + ft1 * wg1 + ft2 * wg2 + ft3 * wg3;
        float c1 = wh * a1u;
        float c2 = wh * a2u;
        float h1 = b1u + ft0 * w10 + ft1 * w11 + ft2 * w12 + ft3 * w13;
        h1 = fmaxf(h1, 0.0f);
        sh1[nl8][u] = h1;
        #pragma unroll
        for (int off = 16; off > 0; off >>= 1) {
            c1 += __shfl_down_sync(0xffffffffu, c1, off);
            c2 += __shfl_down_sync(0xffffffffu, c2, off);
        }
        int half = u >> 5;
        if ((u & 31) == 0) { sr[nl8][half][0] = c1; sr[nl8][half][1] = c2; }
        __syncthreads();
        float h2 = b2u;
        #pragma unroll 8
        for (int k2 = 0; k2 < HID; k2++) h2 += sh1[nl8][k2] * sW2[k2 * HID + u];
        h2 = fmaxf(h2, 0.0f);
        float cp = h2 * w3u;
        #pragma unroll
        for (int off = 16; off > 0; off >>= 1)
            cp += __shfl_down_sync(0xffffffffu, cp, off);
        if ((u & 31) == 0) sr[nl8][half][2] = cp;
        __syncthreads();
        if (node < n1 && u == 0) {
            g_f1[node] = sr[nl8][0][0] + sr[nl8][1][0];
            g_f2[node] = sr[nl8][0][1] + sr[nl8][1][1];
            float Ci = sr[nl8][0][2] + sr[nl8][1][2] + b3s;
            g_Ci[node] = Ci;
            out_Ci[node] = Ci;
        }
        __syncthreads();
    }
}

// ============ K2: edge constants + BP loop + readout dump ==================
__global__ __launch_bounds__(NTHR, 1)
void k_bp(const float* __restrict__ bias, const int* __restrict__ col,
          int N, int E,
          float* __restrict__ out_readout, float* __restrict__ out_dom)
{
    __shared__ float sn[32];
    const int tid = threadIdx.x;
    const int b = blockIdx.x;
    const int DEG = E / N;
    unsigned bar_tgt = NBLK;

    const int npb = (N + NBLK - 1) / NBLK;
    const int n0 = b * npb;
    const int n1 = min(N, n0 + npb);
    const bool live = (n0 < n1);

    // ----- P3: per-thread edge/node constants + x0 (plain loads: new launch,
    //           L1 is flushed per-launch so K1's writes are visible) -----
    const int jl = tid >> 4;
    const int k = tid & 15;
    const int jn = n0 + jl;
    const bool nv = live && (jl < npb) && (jn < n1);
    const bool ev = nv && (k < DEG);
    int e_out = 0, i_nb = 0;
    float jc = 0.0f, C = 0.0f;
    if (ev) {
        e_out = jn * DEG + k;
        i_nb = col[e_out];
        float a = g_f1[jn] + g_f2[i_nb];
        float bb = g_f1[i_nb] + g_f2[jn];
        a = (a >= 0.0f) ? a : 0.2f * a;       // leaky_relu 0.2
        bb = (bb >= 0.0f) ? bb : 0.2f * bb;
        C = 0.5f * (__expf(a) + __expf(bb));  // symmetric both directions
        jc = g_Jv[e_out] / C;
        g_Cij[e_out] = C;
        g_jc[e_out] = jc;
    }
    float csum = ev ? C : 0.0f;
    #pragma unroll
    for (int off = 8; off > 0; off >>= 1)
        csum += __shfl_xor_sync(0xffffffffu, csum, off);
    float rdom = 1.0f, bx0 = 0.0f, bx1 = 0.0f, x0 = 0.0f, x1 = 0.0f;
    if (nv) {
        float d = g_Ci[jn] + csum;
        float sgn = (d > 0.0f) ? 1.0f : ((d < 0.0f) ? -1.0f : 0.0f);
        float dom = sgn * fmaxf(fabsf(d), 0.1f);
        rdom = 1.0f / dom;
        float bs = bias[jn] * rdom;
        bx0 = -bs; bx1 = bs;
        x0 = bx0; x1 = bx1;                   // em0 = 0 -> nm = 0
        if (k == 0) {
            g_x2[jn] = make_float2(x0, x1);
            out_dom[jn] = dom;
        }
    }
    float ei0 = 0.0f, ei1 = 0.0f;             // em on in-edge  (i_nb -> jn)
    float eo0 = 0.0f, eo1 = 0.0f;             // em on out-edge (jn -> i_nb)
    gbar(bar_tgt);                                          // x0 global

    // ----- BP loop: log-domain, registers only, 1 barrier/step -----
    for (int t = 0; t < NSTEP; t++) {
        float ni0 = 0.0f, ni1 = 0.0f;
        if (ev) {
            float2 xi = __ldcg(&g_x2[i_nb]); // only remote data per step
            float d0 = x0 - ei0, d1 = x1 - ei1;
            float lt0 = fmaxf(jc + d0, d1 - jc);
            float lt1 = fmaxf(d0 - jc, jc + d1);
            float lse = fmaxf(lt0, lt1)
                      + __logf(1.0f + __expf(-fabsf(lt0 - lt1)));
            float no0 = C * (lt0 - lse);
            float no1 = C * (lt1 - lse);
            float c0 = xi.x - eo0, c1 = xi.y - eo1;
            float ls0 = fmaxf(jc + c0, c1 - jc);
            float ls1 = fmaxf(c0 - jc, jc + c1);
            float lsi = fmaxf(ls0, ls1)
                      + __logf(1.0f + __expf(-fabsf(ls0 - ls1)));
            ni0 = C * (ls0 - lsi);
            ni1 = C * (ls1 - lsi);
            eo0 = no0; eo1 = no1;
            ei0 = ni0; ei1 = ni1;
        }
        float m0 = ni0, m1 = ni1;
        #pragma unroll
        for (int off = 8; off > 0; off >>= 1) {
            m0 += __shfl_xor_sync(0xffffffffu, m0, off);
            m1 += __shfl_xor_sync(0xffffffffu, m1, off);
        }
        if (nv) {
            x0 = bx0 + m0 * rdom;
            x1 = bx1 + m1 * rdom;
            if (k == 0 && t != NSTEP - 1) g_x2[jn] = make_float2(x0, x1);
        }
        if (t != NSTEP - 1) gbar(bar_tgt);                  // 9 in-loop barriers
    }

    // ----- P5: dump messages + readout (+log) + node entropy partial -----
    if (ev) g_em2[e_out] = make_float2(eo0, eo1);
    float pnode = 0.0f;
    if (nv && k == 0) {
        float lse = fmaxf(x0, x1) + __logf(1.0f + __expf(-fabsf(x0 - x1)));
        float lr0 = x0 - lse, lr1 = x1 - lse;
        float r0 = __expf(lr0), r1 = __expf(lr1);
        out_readout[2 * jn] = r0;
        out_readout[2 * jn + 1] = r1;
        g_lr2[jn] = make_float2(lr0, lr1);
        pnode = g_Ci[jn] * (-(r0 * lr0 + r1 * lr1));
    }
    if (tid < 32) sn[tid] = 0.0f;
    __syncthreads();
    if (nv && k == 0 && jl < 32) sn[jl] = pnode;
    __syncthreads();
    if (tid == 0) {
        float s = 0.0f;
        for (int i2 = 0; i2 < npb && i2 < 32; i2++) s += sn[i2];
        g_npart[b] = s;
    }
}

// ============ K3: pairwise readout + edge entropy + finalize ===============
__global__ __launch_bounds__(NTHR, 1)
void k_pair(const int* __restrict__ rev, const int* __restrict__ ru,
            const int* __restrict__ cu, const int* __restrict__ u2e,
            int Eu,
            float* __restrict__ out_pw, float* __restrict__ out_cij,
            float* __restrict__ out_scal)
{
    __shared__ float sred[NTHR];
    const int tid = threadIdx.x;
    const int b = blockIdx.x;
    const int gsize = NBLK * NTHR;

    float pedge = 0.0f;
    for (int uu = b * NTHR + tid; uu < Eu; uu += gsize) {
        int e = u2e[uu];
        int er = rev[e];
        int ci = cu[uu], rj = ru[uu];
        float Js = g_jc[e];
        float Cu = g_Cij[e];
        float2 eme = g_em2[e];
        float2 emr = g_em2[er];
        float2 li = g_lr2[ci];
        float2 lj = g_lr2[rj];
        float lti0 = li.x - eme.x, lti1 = li.y - eme.y;
        float ltj0 = lj.x - emr.x, ltj1 = lj.y - emr.y;
        float lp00 =  Js + lti0 + ltj0;
        float lp01 = -Js + lti1 + ltj0;
        float lp10 = -Js + lti0 + ltj1;
        float lp11 =  Js + lti1 + ltj1;
        float m = fmaxf(fmaxf(lp00, lp01), fmaxf(lp10, lp11));
        float e00 = __expf(lp00 - m), e01 = __expf(lp01 - m);
        float e10 = __expf(lp10 - m), e11 = __expf(lp11 - m);
        float S = e00 + e01 + e10 + e11;
        float invS = __frcp_rn(S);
        float lS = __logf(S);
        float q00 = e00 * invS, q01 = e01 * invS;
        float q10 = e10 * invS, q11 = e11 * invS;
        out_pw[4 * uu]     = q00;
        out_pw[4 * uu + 1] = q01;
        out_pw[4 * uu + 2] = q10;
        out_pw[4 * uu + 3] = q11;
        out_cij[uu] = Cu;
        float eH = -(q00 * (lp00 - m - lS) + q01 * (lp01 - m - lS)
                   + q10 * (lp10 - m - lS) + q11 * (lp11 - m - lS));
        pedge += Cu * eH;
    }
    sred[tid] = pedge;
    __syncthreads();
    #pragma unroll
    for (int off = NTHR / 2; off > 0; off >>= 1) {
        if (tid < off) sred[tid] += sred[tid + off];
        __syncthreads();
    }

    if (tid == 0) {
        g_epart[b] = sred[0];
        unsigned prev;
        asm volatile("atom.acq_rel.gpu.add.u32 %0, [%1], %2;"
                     : "=r"(prev) : "l"(&g_done), "r"(1u) : "memory");
        if (prev == (unsigned)(NBLK - 1)) {
            float ne = 0.0f, ed = 0.0f;
            for (int i2 = 0; i2 < NBLK; i2++) ne += __ldcg(&g_npart[i2]);
            for (int i2 = 0; i2 < NBLK; i2++) ed += __ldcg(&g_epart[i2]);
            out_scal[0] = ne + ed;
            out_scal[1] = ne;
            out_scal[2] = ed;
        }
    }
}

// ---------------- launcher ---------------------------------------------------
extern "C" void kernel_launch(void* const* d_in, const int* in_sizes, int n_in,
                              void* d_out, int out_size) {
    const float* J     = (const float*)d_in[0];
    const float* bias  = (const float*)d_in[1];
    const float* gat_W = (const float*)d_in[2];
    const float* gat_a = (const float*)d_in[3];
    const float* W1    = (const float*)d_in[4];
    const float* b1    = (const float*)d_in[5];
    const float* W2    = (const float*)d_in[6];
    const float* b2    = (const float*)d_in[7];
    const float* W3    = (const float*)d_in[8];
    const float* b3    = (const float*)d_in[9];
    const int*   col   = (const int*)d_in[11];
    const int*   rev   = (const int*)d_in[12];
    const int*   ru    = (const int*)d_in[13];
    const int*   cu    = (const int*)d_in[14];
    const int*   u2e   = (const int*)d_in[15];

    int N  = in_sizes[1];
    int E  = in_sizes[10];
    int Eu = in_sizes[13];

    float* out = (float*)d_out;
    float* out_readout = out;                    // [N,2]
    float* out_pw      = out + 2 * N;            // [Eu,4]
    float* out_scal    = out + 2 * N + 4 * Eu;   // 3 scalars
    float* out_Ci      = out_scal + 3;           // [N]
    float* out_cij     = out_Ci + N;             // [Eu]
    float* out_dom     = out_cij + Eu;           // [N]

    k_feat<<<NBLK, NTHR>>>(J, bias, gat_W, gat_a, W1, b1, W2, b2, W3, b3,
                           col, N, E, out_Ci);
    k_bp<<<NBLK, NTHR>>>(bias, col, N, E, out_readout, out_dom);
    k_pair<<<NBLK, NTHR>>>(rev, ru, cu, u2e, Eu, out_pw, out_cij, out_scal);
}

// round 16
// speedup vs baseline: 1.3461x; 1.0572x over previous
#include <cuda_runtime.h>
#include <math.h>

#define HID 64
#define NMAX 8192
#define EMAX 131072
#define NBLK 144      // K1/K3 grid
#define NBLK2 64      // K2 grid (2 edges per thread)
#define NTHR 512
#define NSTEP 10
#define DEGC 16       // compile-time degree fast path

// ---------------- device scratch (no allocation allowed) ----------------
__device__ float  g_Jv[EMAX];
__device__ float  g_Cij[EMAX];
__device__ float  g_jc[EMAX];
__device__ float2 g_em2[EMAX];       // final messages
__device__ float  g_f1[NMAX];
__device__ float  g_f2[NMAX];
__device__ float  g_Ci[NMAX];
__device__ float2 g_x2[NMAX];        // x = bx + nm/dom (the per-step global)
__device__ float2 g_lr2[NMAX];       // log-readout
__device__ float  g_npart[NBLK2];
__device__ float  g_epart[NBLK];
__device__ __align__(128) unsigned g_count;  // monotonic barrier counter
__device__ __align__(128) unsigned g_done;   // K3 finalize counter

// Monotonic-counter grid barrier (K2 only). Arrival = red.release (no RTT on
// the critical path). Waiters poll relaxed then one acquire load. No in-kernel
// reset (no ABA); K1 zeroes g_count each launch while K2 is quiescent.
__device__ __forceinline__ void gbar(unsigned& tgt) {
    __syncthreads();
    if (threadIdx.x == 0) {
        asm volatile("red.release.gpu.add.u32 [%0], %1;"
                     :: "l"(&g_count), "r"(1u) : "memory");
        unsigned v;
        do {
            asm volatile("ld.relaxed.gpu.u32 %0, [%1];"
                         : "=r"(v) : "l"(&g_count) : "memory");
        } while (v < tgt);
        asm volatile("ld.acquire.gpu.u32 %0, [%1];"
                     : "=r"(v) : "l"(&g_count) : "memory");
    }
    tgt += NBLK2;
    __syncthreads();
}

// One directed BP message in log-domain: given x (node potential), e_old
// (old message on the OPPOSITE direction of this edge), returns new message.
__device__ __forceinline__ void bp_msg(float jc, float Cc,
                                       float xa, float xb,
                                       float eold0, float eold1,
                                       float& n0, float& n1) {
    float d0 = xa - eold0, d1 = xb - eold1;
    float l0 = fmaxf(jc + d0, d1 - jc);
    float l1 = fmaxf(d0 - jc, jc + d1);
    float ls = fmaxf(l0, l1) + __logf(1.0f + __expf(-fabsf(l0 - l1)));
    n0 = Cc * (l0 - ls);
    n1 = Cc * (l1 - ls);
}

// ============ K1: J gather + node features + GAT f1/f2 + Ci MLP ============
__global__ __launch_bounds__(NTHR, 1)
void k_feat(const float* __restrict__ J, const float* __restrict__ bias,
            const float* __restrict__ gat_W, const float* __restrict__ gat_a,
            const float* __restrict__ W1, const float* __restrict__ b1,
            const float* __restrict__ W2, const float* __restrict__ b2,
            const float* __restrict__ W3, const float* __restrict__ b3,
            const int* __restrict__ col, int N, int E,
            float* __restrict__ out_Ci)
{
    __shared__ float sh1[8][HID];
    __shared__ float sr[8][2][3];
    __shared__ float sJv[NTHR];

    const int tid = threadIdx.x;
    const int b = blockIdx.x;
    const int DEG = E / N;
    if (b == 0 && tid == 0) { g_count = 0u; g_done = 0u; }  // quiescent reset

    const int npb = (N + NBLK - 1) / NBLK;
    const int n0 = b * npb;
    const int n1 = min(N, n0 + npb);
    if (n0 >= n1) return;
    const int es = n0 * DEG;

    for (int e = es + tid; e < n1 * DEG; e += NTHR) {
        int r = e / DEG;
        float v = J[(long long)r * N + col[e]];
        sJv[e - es] = v;
        g_Jv[e] = v;
    }

    int u = tid & 63;
    int nl8 = tid >> 6;
    // W2 column in registers: thread u caches W2[k][u] for all k. One
    // coalesced global pass, reused for every node -> h2 loop has NO W2
    // LDS, only conflict-free broadcast sh1 loads.
    float w2r[HID];
    #pragma unroll
    for (int k2 = 0; k2 < HID; k2++) w2r[k2] = W2[k2 * HID + u];
    float wg0 = gat_W[u],           wg1 = gat_W[HID + u];
    float wg2 = gat_W[2 * HID + u], wg3 = gat_W[3 * HID + u];
    float a1u = gat_a[u],           a2u = gat_a[HID + u];
    float w10 = W1[u],              w11 = W1[HID + u];
    float w12 = W1[2 * HID + u],    w13 = W1[3 * HID + u];
    float b1u = b1[u], b2u = b2[u], w3u = W3[u], b3s = b3[0];
    __syncthreads();

    const int npass = (npb + 7) / 8;
    for (int p = 0; p < npass; p++) {
        int node = n0 + p * 8 + nl8;
        int nc = node < n1 ? node : n1 - 1;
        float bb = bias[nc];
        int s0 = (nc - n0) * DEG;
        float Jsum = 0.0f;
        if (DEG == DEGC) {
            #pragma unroll
            for (int k2 = 0; k2 < DEGC; k2++) Jsum += sJv[s0 + k2];
        } else {
            for (int k2 = 0; k2 < DEG; k2++) Jsum += sJv[s0 + k2];
        }
        float ft0 = -bb, ft1 = bb, ft2 = (float)DEG, ft3 = Jsum;
        float wh = ft0 * wg0 + ft1 * wg1 + ft2 * wg2 + ft3 * wg3;
        float c1 = wh * a1u;
        float c2 = wh * a2u;
        float h1 = b1u + ft0 * w10 + ft1 * w11 + ft2 * w12 + ft3 * w13;
        h1 = fmaxf(h1, 0.0f);
        sh1[nl8][u] = h1;
        #pragma unroll
        for (int off = 16; off > 0; off >>= 1) {
            c1 += __shfl_down_sync(0xffffffffu, c1, off);
            c2 += __shfl_down_sync(0xffffffffu, c2, off);
        }
        int half = u >> 5;
        if ((u & 31) == 0) { sr[nl8][half][0] = c1; sr[nl8][half][1] = c2; }
        __syncthreads();
        float h2 = b2u;
        #pragma unroll
        for (int k2 = 0; k2 < HID; k2++) h2 += sh1[nl8][k2] * w2r[k2];
        h2 = fmaxf(h2, 0.0f);
        float cp = h2 * w3u;
        #pragma unroll
        for (int off = 16; off > 0; off >>= 1)
            cp += __shfl_down_sync(0xffffffffu, cp, off);
        if ((u & 31) == 0) sr[nl8][half][2] = cp;
        __syncthreads();
        if (node < n1 && u == 0) {
            g_f1[node] = sr[nl8][0][0] + sr[nl8][1][0];
            g_f2[node] = sr[nl8][0][1] + sr[nl8][1][1];
            float Ci = sr[nl8][0][2] + sr[nl8][1][2] + b3s;
            g_Ci[node] = Ci;
            out_Ci[node] = Ci;
        }
        __syncthreads();
    }
}

// ============ K2: edge constants + BP loop + readout dump ==================
// 2 edges per thread: 8 lanes per node, 64 nodes per block, 64 blocks.
__global__ __launch_bounds__(NTHR, 1)
void k_bp(const float* __restrict__ bias, const int* __restrict__ col,
          int N, int E,
          float* __restrict__ out_readout, float* __restrict__ out_dom)
{
    __shared__ float sn[64];
    const int tid = threadIdx.x;
    const int b = blockIdx.x;
    const int DEG = E / N;
    unsigned bar_tgt = NBLK2;

    const int npb = (N + NBLK2 - 1) / NBLK2;   // 64
    const int n0 = b * npb;
    const int n1 = min(N, n0 + npb);
    const bool live = (n0 < n1);

    const int jl = tid >> 3;          // node-local 0..63
    const int k = tid & 7;            // lane slot -> edges k and k+8
    const int jn = n0 + jl;
    const bool nv = live && (jl < npb) && (jn < n1);
    const bool ev0 = nv && (k < DEG);
    const bool ev1 = nv && (k + 8 < DEG);
    int e0 = 0, e1 = 0, i0 = 0, i1 = 0;
    float jc0 = 0.0f, C0 = 0.0f, jc1 = 0.0f, C1 = 0.0f;
    if (ev0) {
        e0 = jn * DEG + k;
        i0 = col[e0];
        float a = g_f1[jn] + g_f2[i0];
        float bb = g_f1[i0] + g_f2[jn];
        a = (a >= 0.0f) ? a : 0.2f * a;       // leaky_relu 0.2
        bb = (bb >= 0.0f) ? bb : 0.2f * bb;
        C0 = 0.5f * (__expf(a) + __expf(bb)); // symmetric both directions
        jc0 = g_Jv[e0] / C0;
        g_Cij[e0] = C0;
        g_jc[e0] = jc0;
    }
    if (ev1) {
        e1 = jn * DEG + k + 8;
        i1 = col[e1];
        float a = g_f1[jn] + g_f2[i1];
        float bb = g_f1[i1] + g_f2[jn];
        a = (a >= 0.0f) ? a : 0.2f * a;
        bb = (bb >= 0.0f) ? bb : 0.2f * bb;
        C1 = 0.5f * (__expf(a) + __expf(bb));
        jc1 = g_Jv[e1] / C1;
        g_Cij[e1] = C1;
        g_jc[e1] = jc1;
    }
    float csum = C0 + C1;
    #pragma unroll
    for (int off = 4; off > 0; off >>= 1)
        csum += __shfl_xor_sync(0xffffffffu, csum, off);
    float rdom = 1.0f, bx0 = 0.0f, bx1 = 0.0f, x0 = 0.0f, x1 = 0.0f;
    if (nv) {
        float d = g_Ci[jn] + csum;
        float sgn = (d > 0.0f) ? 1.0f : ((d < 0.0f) ? -1.0f : 0.0f);
        float dom = sgn * fmaxf(fabsf(d), 0.1f);
        rdom = 1.0f / dom;
        float bs = bias[jn] * rdom;
        bx0 = -bs; bx1 = bs;
        x0 = bx0; x1 = bx1;                   // em0 = 0 -> nm = 0
        if (k == 0) {
            g_x2[jn] = make_float2(x0, x1);
            out_dom[jn] = dom;
        }
    }
    float ei00 = 0.0f, ei01 = 0.0f, eo00 = 0.0f, eo01 = 0.0f;  // edge 0
    float ei10 = 0.0f, ei11 = 0.0f, eo10 = 0.0f, eo11 = 0.0f;  // edge 1
    gbar(bar_tgt);                                          // x0 global

    // BP loop: per step, compute in-messages (use OLD eo) and out-messages
    // (use OLD ei) into fresh locals, then commit all at once.
    for (int t = 0; t < NSTEP; t++) {
        float ni00 = 0.0f, ni01 = 0.0f, no00 = 0.0f, no01 = 0.0f;
        float ni10 = 0.0f, ni11 = 0.0f, no10 = 0.0f, no11 = 0.0f;
        if (ev0) {
            float2 xi = __ldcg(&g_x2[i0]);
            bp_msg(jc0, C0, xi.x, xi.y, eo00, eo01, ni00, ni01); // in  (i0->jn)
            bp_msg(jc0, C0, x0,   x1,   ei00, ei01, no00, no01); // out (jn->i0)
        }
        if (ev1) {
            float2 xi = __ldcg(&g_x2[i1]);
            bp_msg(jc1, C1, xi.x, xi.y, eo10, eo11, ni10, ni11); // in  (i1->jn)
            bp_msg(jc1, C1, x0,   x1,   ei10, ei11, no10, no11); // out (jn->i1)
        }
        eo00 = no00; eo01 = no01; ei00 = ni00; ei01 = ni01;
        eo10 = no10; eo11 = no11; ei10 = ni10; ei11 = ni11;
        float m0 = ni00 + ni10;
        float m1 = ni01 + ni11;
        #pragma unroll
        for (int off = 4; off > 0; off >>= 1) {
            m0 += __shfl_xor_sync(0xffffffffu, m0, off);
            m1 += __shfl_xor_sync(0xffffffffu, m1, off);
        }
        if (nv) {
            x0 = bx0 + m0 * rdom;
            x1 = bx1 + m1 * rdom;
            if (k == 0 && t != NSTEP - 1) g_x2[jn] = make_float2(x0, x1);
        }
        if (t != NSTEP - 1) gbar(bar_tgt);                  // 9 in-loop barriers
    }

    // ----- dump messages + readout (+log) + node entropy partial -----
    if (ev0) g_em2[e0] = make_float2(eo00, eo01);
    if (ev1) g_em2[e1] = make_float2(eo10, eo11);
    float pnode = 0.0f;
    if (nv && k == 0) {
        float lse = fmaxf(x0, x1) + __logf(1.0f + __expf(-fabsf(x0 - x1)));
        float lr0 = x0 - lse, lr1 = x1 - lse;
        float r0 = __expf(lr0), r1 = __expf(lr1);
        out_readout[2 * jn] = r0;
        out_readout[2 * jn + 1] = r1;
        g_lr2[jn] = make_float2(lr0, lr1);
        pnode = g_Ci[jn] * (-(r0 * lr0 + r1 * lr1));
    }
    if (tid < 64) sn[tid] = 0.0f;
    __syncthreads();
    if (nv && k == 0 && jl < 64) sn[jl] = pnode;
    __syncthreads();
    if (tid == 0) {
        float s = 0.0f;
        for (int i2 = 0; i2 < npb && i2 < 64; i2++) s += sn[i2];
        g_npart[b] = s;
    }
}

// ============ K3: pairwise readout + edge entropy + finalize ===============
__global__ __launch_bounds__(NTHR, 1)
void k_pair(const int* __restrict__ rev, const int* __restrict__ ru,
            const int* __restrict__ cu, const int* __restrict__ u2e,
            int Eu,
            float* __restrict__ out_pw, float* __restrict__ out_cij,
            float* __restrict__ out_scal)
{
    __shared__ float sred[NTHR];
    const int tid = threadIdx.x;
    const int b = blockIdx.x;
    const int gsize = NBLK * NTHR;

    float pedge = 0.0f;
    for (int uu = b * NTHR + tid; uu < Eu; uu += gsize) {
        int e = u2e[uu];
        int er = rev[e];
        int ci = cu[uu], rj = ru[uu];
        float Js = g_jc[e];
        float Cu = g_Cij[e];
        float2 eme = g_em2[e];
        float2 emr = g_em2[er];
        float2 li = g_lr2[ci];
        float2 lj = g_lr2[rj];
        float lti0 = li.x - eme.x, lti1 = li.y - eme.y;
        float ltj0 = lj.x - emr.x, ltj1 = lj.y - emr.y;
        float lp00 =  Js + lti0 + ltj0;
        float lp01 = -Js + lti1 + ltj0;
        float lp10 = -Js + lti0 + ltj1;
        float lp11 =  Js + lti1 + ltj1;
        float m = fmaxf(fmaxf(lp00, lp01), fmaxf(lp10, lp11));
        float e00 = __expf(lp00 - m), e01 = __expf(lp01 - m);
        float e10 = __expf(lp10 - m), e11 = __expf(lp11 - m);
        float S = e00 + e01 + e10 + e11;
        float invS = __frcp_rn(S);
        float lS = __logf(S);
        float q00 = e00 * invS, q01 = e01 * invS;
        float q10 = e10 * invS, q11 = e11 * invS;
        out_pw[4 * uu]     = q00;
        out_pw[4 * uu + 1] = q01;
        out_pw[4 * uu + 2] = q10;
        out_pw[4 * uu + 3] = q11;
        out_cij[uu] = Cu;
        float eH = -(q00 * (lp00 - m - lS) + q01 * (lp01 - m - lS)
                   + q10 * (lp10 - m - lS) + q11 * (lp11 - m - lS));
        pedge += Cu * eH;
    }
    sred[tid] = pedge;
    __syncthreads();
    #pragma unroll
    for (int off = NTHR / 2; off > 0; off >>= 1) {
        if (tid < off) sred[tid] += sred[tid + off];
        __syncthreads();
    }

    if (tid == 0) {
        g_epart[b] = sred[0];
        unsigned prev;
        asm volatile("atom.acq_rel.gpu.add.u32 %0, [%1], %2;"
                     : "=r"(prev) : "l"(&g_done), "r"(1u) : "memory");
        if (prev == (unsigned)(NBLK - 1)) {
            float ne = 0.0f, ed = 0.0f;
            for (int i2 = 0; i2 < NBLK2; i2++) ne += __ldcg(&g_npart[i2]);
            for (int i2 = 0; i2 < NBLK; i2++) ed += __ldcg(&g_epart[i2]);
            out_scal[0] = ne + ed;
            out_scal[1] = ne;
            out_scal[2] = ed;
        }
    }
}

// ---------------- launcher ---------------------------------------------------
extern "C" void kernel_launch(void* const* d_in, const int* in_sizes, int n_in,
                              void* d_out, int out_size) {
    const float* J     = (const float*)d_in[0];
    const float* bias  = (const float*)d_in[1];
    const float* gat_W = (const float*)d_in[2];
    const float* gat_a = (const float*)d_in[3];
    const float* W1    = (const float*)d_in[4];
    const float* b1    = (const float*)d_in[5];
    const float* W2    = (const float*)d_in[6];
    const float* b2    = (const float*)d_in[7];
    const float* W3    = (const float*)d_in[8];
    const float* b3    = (const float*)d_in[9];
    const int*   col   = (const int*)d_in[11];
    const int*   rev   = (const int*)d_in[12];
    const int*   ru    = (const int*)d_in[13];
    const int*   cu    = (const int*)d_in[14];
    const int*   u2e   = (const int*)d_in[15];

    int N  = in_sizes[1];
    int E  = in_sizes[10];
    int Eu = in_sizes[13];

    float* out = (float*)d_out;
    float* out_readout = out;                    // [N,2]
    float* out_pw      = out + 2 * N;            // [Eu,4]
    float* out_scal    = out + 2 * N + 4 * Eu;   // 3 scalars
    float* out_Ci      = out_scal + 3;           // [N]
    float* out_cij     = out_Ci + N;             // [Eu]
    float* out_dom     = out_cij + Eu;           // [N]

    k_feat<<<NBLK, NTHR>>>(J, bias, gat_W, gat_a, W1, b1, W2, b2, W3, b3,
                           col, N, E, out_Ci);
    k_bp<<<NBLK2, NTHR>>>(bias, col, N, E, out_readout, out_dom);
    k_pair<<<NBLK, NTHR>>>(rev, ru, cu, u2e, Eu, out_pw, out_cij, out_scal);
}

// round 17
// speedup vs baseline: 1.4083x; 1.0463x over previous
#include <cuda_runtime.h>
#include <math.h>

#define HID 64
#define NMAX 8192
#define EMAX 131072
#define NBLK 144      // K1 grid
#define NBLK2 64      // K2 grid (2 edges per thread)
#define NTHR 512
#define NSTEP 10
#define DEGC 16       // compile-time degree fast path

// ---------------- device scratch (no allocation allowed) ----------------
__device__ float  g_Jv[EMAX];
__device__ float  g_Cij[EMAX];
__device__ float  g_jc[EMAX];
__device__ float2 g_em2[EMAX];       // final messages
__device__ float  g_f1[NMAX];
__device__ float  g_f2[NMAX];
__device__ float  g_Ci[NMAX];
__device__ float2 g_xb[2][NMAX];     // double-buffered x (step parity)
__device__ float2 g_lr2[NMAX];       // log-readout
__device__ float  g_npart[NBLK2];
__device__ float  g_epart[NBLK2];
__device__ __align__(128) unsigned g_count;  // monotonic barrier counter
__device__ __align__(128) unsigned g_done;   // finalize counter

// Split grid barrier: arrival = red.release right after the x store; the
// wait (poll) is deferred past local-only compute, so detection usually
// costs one L2 round trip. Monotonic counter -> no reset/ABA races; K1
// zeroes it each launch while K2 is quiescent.
__device__ __forceinline__ void gbar_arrive() {
    asm volatile("red.release.gpu.add.u32 [%0], %1;"
                 :: "l"(&g_count), "r"(1u) : "memory");
}
__device__ __forceinline__ void gbar_wait(unsigned tgt) {
    unsigned v;
    do {
        asm volatile("ld.relaxed.gpu.u32 %0, [%1];"
                     : "=r"(v) : "l"(&g_count) : "memory");
    } while (v < tgt);
    asm volatile("ld.acquire.gpu.u32 %0, [%1];"
                 : "=r"(v) : "l"(&g_count) : "memory");
}

// One directed BP message in log-domain.
__device__ __forceinline__ void bp_msg(float jc, float Cc,
                                       float xa, float xb,
                                       float eold0, float eold1,
                                       float& n0, float& n1) {
    float d0 = xa - eold0, d1 = xb - eold1;
    float l0 = fmaxf(jc + d0, d1 - jc);
    float l1 = fmaxf(d0 - jc, jc + d1);
    float ls = fmaxf(l0, l1) + __logf(1.0f + __expf(-fabsf(l0 - l1)));
    n0 = Cc * (l0 - ls);
    n1 = Cc * (l1 - ls);
}

// ============ K1: J gather + node features + GAT f1/f2 + Ci MLP ============
__global__ __launch_bounds__(NTHR, 1)
void k_feat(const float* __restrict__ J, const float* __restrict__ bias,
            const float* __restrict__ gat_W, const float* __restrict__ gat_a,
            const float* __restrict__ W1, const float* __restrict__ b1,
            const float* __restrict__ W2, const float* __restrict__ b2,
            const float* __restrict__ W3, const float* __restrict__ b3,
            const int* __restrict__ col, int N, int E,
            float* __restrict__ out_Ci)
{
    __shared__ float sh1[8][HID];
    __shared__ float sr[8][2][3];
    __shared__ float sJv[NTHR];

    const int tid = threadIdx.x;
    const int b = blockIdx.x;
    const int DEG = E / N;
    if (b == 0 && tid == 0) { g_count = 0u; g_done = 0u; }  // quiescent reset

    const int npb = (N + NBLK - 1) / NBLK;
    const int n0 = b * npb;
    const int n1 = min(N, n0 + npb);
    if (n0 >= n1) return;
    const int es = n0 * DEG;

    for (int e = es + tid; e < n1 * DEG; e += NTHR) {
        int r = e / DEG;
        float v = J[(long long)r * N + col[e]];
        sJv[e - es] = v;
        g_Jv[e] = v;
    }

    int u = tid & 63;
    int nl8 = tid >> 6;
    // W2 column in registers (coalesced across threads per k).
    float w2r[HID];
    #pragma unroll
    for (int k2 = 0; k2 < HID; k2++) w2r[k2] = W2[k2 * HID + u];
    float wg0 = gat_W[u],           wg1 = gat_W[HID + u];
    float wg2 = gat_W[2 * HID + u], wg3 = gat_W[3 * HID + u];
    float a1u = gat_a[u],           a2u = gat_a[HID + u];
    float w10 = W1[u],              w11 = W1[HID + u];
    float w12 = W1[2 * HID + u],    w13 = W1[3 * HID + u];
    float b1u = b1[u], b2u = b2[u], w3u = W3[u], b3s = b3[0];
    __syncthreads();

    const int npass = (npb + 7) / 8;
    for (int p = 0; p < npass; p++) {
        int node = n0 + p * 8 + nl8;
        int nc = node < n1 ? node : n1 - 1;
        float bb = bias[nc];
        float Jsum = 0.0f;
        if (DEG == DEGC) {
            const float4* jv4 = reinterpret_cast<const float4*>(
                &sJv[(nc - n0) * DEGC]);
            #pragma unroll
            for (int k2 = 0; k2 < DEGC / 4; k2++) {
                float4 v = jv4[k2];
                Jsum += v.x + v.y + v.z + v.w;
            }
        } else {
            int s0 = (nc - n0) * DEG;
            for (int k2 = 0; k2 < DEG; k2++) Jsum += sJv[s0 + k2];
        }
        float ft0 = -bb, ft1 = bb, ft2 = (float)DEG, ft3 = Jsum;
        float wh = ft0 * wg0 + ft1 * wg1 + ft2 * wg2 + ft3 * wg3;
        float c1 = wh * a1u;
        float c2 = wh * a2u;
        float h1 = b1u + ft0 * w10 + ft1 * w11 + ft2 * w12 + ft3 * w13;
        h1 = fmaxf(h1, 0.0f);
        sh1[nl8][u] = h1;
        #pragma unroll
        for (int off = 16; off > 0; off >>= 1) {
            c1 += __shfl_down_sync(0xffffffffu, c1, off);
            c2 += __shfl_down_sync(0xffffffffu, c2, off);
        }
        int half = u >> 5;
        if ((u & 31) == 0) { sr[nl8][half][0] = c1; sr[nl8][half][1] = c2; }
        __syncthreads();
        float h2 = b2u;
        {
            const float4* h14 = reinterpret_cast<const float4*>(sh1[nl8]);
            #pragma unroll
            for (int k2 = 0; k2 < HID / 4; k2++) {
                float4 v = h14[k2];
                h2 += v.x * w2r[4 * k2]     + v.y * w2r[4 * k2 + 1]
                    + v.z * w2r[4 * k2 + 2] + v.w * w2r[4 * k2 + 3];
            }
        }
        h2 = fmaxf(h2, 0.0f);
        float cp = h2 * w3u;
        #pragma unroll
        for (int off = 16; off > 0; off >>= 1)
            cp += __shfl_down_sync(0xffffffffu, cp, off);
        if ((u & 31) == 0) sr[nl8][half][2] = cp;
        __syncthreads();
        if (node < n1 && u == 0) {
            g_f1[node] = sr[nl8][0][0] + sr[nl8][1][0];
            g_f2[node] = sr[nl8][0][1] + sr[nl8][1][1];
            float Ci = sr[nl8][0][2] + sr[nl8][1][2] + b3s;
            g_Ci[node] = Ci;
            out_Ci[node] = Ci;
        }
        __syncthreads();
    }
}

// ===== K2: edge constants + pipelined BP loop + readout + pairwise =========
__global__ __launch_bounds__(NTHR, 1)
void k_bp(const float* __restrict__ bias, const int* __restrict__ col,
          const int* __restrict__ rev, const int* __restrict__ ru,
          const int* __restrict__ cu, const int* __restrict__ u2e,
          int N, int E, int Eu,
          float* __restrict__ out_readout, float* __restrict__ out_dom,
          float* __restrict__ out_pw, float* __restrict__ out_cij,
          float* __restrict__ out_scal)
{
    __shared__ float sn[64];
    __shared__ float sred[NTHR];
    const int tid = threadIdx.x;
    const int b = blockIdx.x;
    const int DEG = E / N;
    unsigned tgt = NBLK2;

    const int npb = (N + NBLK2 - 1) / NBLK2;   // 64
    const int n0 = b * npb;
    const int n1 = min(N, n0 + npb);
    const bool live = (n0 < n1);

    const int jl = tid >> 3;          // node-local 0..63
    const int k = tid & 7;            // lane slot -> edges k and k+8
    const int jn = n0 + jl;
    const bool nv = live && (jl < npb) && (jn < n1);
    const bool ev0 = nv && (k < DEG);
    const bool ev1 = nv && (k + 8 < DEG);
    int e0 = 0, e1 = 0, i0 = 0, i1 = 0;
    float jc0 = 0.0f, C0 = 0.0f, jc1 = 0.0f, C1 = 0.0f;
    if (ev0) {
        e0 = jn * DEG + k;
        i0 = col[e0];
        float a = g_f1[jn] + g_f2[i0];
        float bb = g_f1[i0] + g_f2[jn];
        a = (a >= 0.0f) ? a : 0.2f * a;       // leaky_relu 0.2
        bb = (bb >= 0.0f) ? bb : 0.2f * bb;
        C0 = 0.5f * (__expf(a) + __expf(bb)); // symmetric both directions
        jc0 = g_Jv[e0] / C0;
        g_Cij[e0] = C0;
        g_jc[e0] = jc0;
    }
    if (ev1) {
        e1 = jn * DEG + k + 8;
        i1 = col[e1];
        float a = g_f1[jn] + g_f2[i1];
        float bb = g_f1[i1] + g_f2[jn];
        a = (a >= 0.0f) ? a : 0.2f * a;
        bb = (bb >= 0.0f) ? bb : 0.2f * bb;
        C1 = 0.5f * (__expf(a) + __expf(bb));
        jc1 = g_Jv[e1] / C1;
        g_Cij[e1] = C1;
        g_jc[e1] = jc1;
    }
    float csum = C0 + C1;
    #pragma unroll
    for (int off = 4; off > 0; off >>= 1)
        csum += __shfl_xor_sync(0xffffffffu, csum, off);
    float rdom = 1.0f, bx0 = 0.0f, bx1 = 0.0f, x0 = 0.0f, x1 = 0.0f;
    if (nv) {
        float d = g_Ci[jn] + csum;
        float sgn = (d > 0.0f) ? 1.0f : ((d < 0.0f) ? -1.0f : 0.0f);
        float dom = sgn * fmaxf(fabsf(d), 0.1f);
        rdom = 1.0f / dom;
        float bs = bias[jn] * rdom;
        bx0 = -bs; bx1 = bs;
        x0 = bx0; x1 = bx1;                   // em0 = 0 -> nm = 0
        if (k == 0) {
            g_xb[0][jn] = make_float2(x0, x1);
            out_dom[jn] = dom;
        }
    }
    float ei00 = 0.0f, ei01 = 0.0f, eo00 = 0.0f, eo01 = 0.0f;  // edge 0
    float ei10 = 0.0f, ei11 = 0.0f, eo10 = 0.0f, eo11 = 0.0f;  // edge 1
    __syncthreads();
    if (tid == 0) gbar_arrive();              // publish x0 (barrier #1)

    // BP loop, pipelined: out-messages (local-only) BEFORE the barrier wait;
    // only ldcg + in-messages + reduce sit on the post-barrier critical path.
    // Double-buffered x: writers of buf[p] at step t+1 are gated by barrier
    // t+1, which proves all readers of buf[p] (step t) finished -> no WAR.
    for (int t = 0; t < NSTEP; t++) {
        float no00 = 0.0f, no01 = 0.0f, no10 = 0.0f, no11 = 0.0f;
        if (ev0) bp_msg(jc0, C0, x0, x1, ei00, ei01, no00, no01); // out (jn->i0)
        if (ev1) bp_msg(jc1, C1, x0, x1, ei10, ei11, no10, no11); // out (jn->i1)
        if (tid == 0) gbar_wait(tgt);         // usually already satisfied
        tgt += NBLK2;
        __syncthreads();
        const float2* xin = g_xb[t & 1];
        float ni00 = 0.0f, ni01 = 0.0f, ni10 = 0.0f, ni11 = 0.0f;
        if (ev0) {
            float2 xi = __ldcg(&xin[i0]);
            bp_msg(jc0, C0, xi.x, xi.y, eo00, eo01, ni00, ni01);  // in (i0->jn)
        }
        if (ev1) {
            float2 xi = __ldcg(&xin[i1]);
            bp_msg(jc1, C1, xi.x, xi.y, eo10, eo11, ni10, ni11);  // in (i1->jn)
        }
        eo00 = no00; eo01 = no01; ei00 = ni00; ei01 = ni01;
        eo10 = no10; eo11 = no11; ei10 = ni10; ei11 = ni11;
        float m0 = ni00 + ni10;
        float m1 = ni01 + ni11;
        #pragma unroll
        for (int off = 4; off > 0; off >>= 1) {
            m0 += __shfl_xor_sync(0xffffffffu, m0, off);
            m1 += __shfl_xor_sync(0xffffffffu, m1, off);
        }
        if (nv) {
            x0 = bx0 + m0 * rdom;
            x1 = bx1 + m1 * rdom;
        }
        if (t != NSTEP - 1) {
            if (nv && k == 0) g_xb[(t + 1) & 1][jn] = make_float2(x0, x1);
            __syncthreads();
            if (tid == 0) gbar_arrive();
        }
    }

    // ----- P5: dump messages + readout (+log) + node entropy partial -----
    if (ev0) g_em2[e0] = make_float2(eo00, eo01);
    if (ev1) g_em2[e1] = make_float2(eo10, eo11);
    float pnode = 0.0f;
    if (nv && k == 0) {
        float lse = fmaxf(x0, x1) + __logf(1.0f + __expf(-fabsf(x0 - x1)));
        float lr0 = x0 - lse, lr1 = x1 - lse;
        float r0 = __expf(lr0), r1 = __expf(lr1);
        out_readout[2 * jn] = r0;
        out_readout[2 * jn + 1] = r1;
        g_lr2[jn] = make_float2(lr0, lr1);
        pnode = g_Ci[jn] * (-(r0 * lr0 + r1 * lr1));
    }
    if (tid < 64) sn[tid] = 0.0f;
    __syncthreads();
    if (nv && k == 0 && jl < 64) sn[jl] = pnode;
    __syncthreads();
    if (tid == 0) {
        float s = 0.0f;
        for (int i2 = 0; i2 < npb && i2 < 64; i2++) s += sn[i2];
        g_npart[b] = s;
    }
    __syncthreads();
    if (tid == 0) { gbar_arrive(); gbar_wait(tgt); }  // em/lr global
    __syncthreads();

    // ----- P6: pairwise readout + edge entropy (cross-block via ldcg) -----
    float pedge = 0.0f;
    for (int uu = b * NTHR + tid; uu < Eu; uu += NBLK2 * NTHR) {
        int e = u2e[uu];
        int er = rev[e];
        int ci = cu[uu], rj = ru[uu];
        float Js = __ldcg(&g_jc[e]);
        float Cu = __ldcg(&g_Cij[e]);
        float2 eme = __ldcg(&g_em2[e]);
        float2 emr = __ldcg(&g_em2[er]);
        float2 li = __ldcg(&g_lr2[ci]);
        float2 lj = __ldcg(&g_lr2[rj]);
        float lti0 = li.x - eme.x, lti1 = li.y - eme.y;
        float ltj0 = lj.x - emr.x, ltj1 = lj.y - emr.y;
        float lp00 =  Js + lti0 + ltj0;
        float lp01 = -Js + lti1 + ltj0;
        float lp10 = -Js + lti0 + ltj1;
        float lp11 =  Js + lti1 + ltj1;
        float m = fmaxf(fmaxf(lp00, lp01), fmaxf(lp10, lp11));
        float e00 = __expf(lp00 - m), e01 = __expf(lp01 - m);
        float e10 = __expf(lp10 - m), e11 = __expf(lp11 - m);
        float S = e00 + e01 + e10 + e11;
        float invS = __frcp_rn(S);
        float lS = __logf(S);
        float q00 = e00 * invS, q01 = e01 * invS;
        float q10 = e10 * invS, q11 = e11 * invS;
        out_pw[4 * uu]     = q00;
        out_pw[4 * uu + 1] = q01;
        out_pw[4 * uu + 2] = q10;
        out_pw[4 * uu + 3] = q11;
        out_cij[uu] = Cu;
        float eH = -(q00 * (lp00 - m - lS) + q01 * (lp01 - m - lS)
                   + q10 * (lp10 - m - lS) + q11 * (lp11 - m - lS));
        pedge += Cu * eH;
    }
    sred[tid] = pedge;
    __syncthreads();
    #pragma unroll
    for (int off = NTHR / 2; off > 0; off >>= 1) {
        if (tid < off) sred[tid] += sred[tid + off];
        __syncthreads();
    }

    // ----- finalize scalars: last-arriving block -----
    if (tid == 0) {
        g_epart[b] = sred[0];
        unsigned prev;
        asm volatile("atom.acq_rel.gpu.add.u32 %0, [%1], %2;"
                     : "=r"(prev) : "l"(&g_done), "r"(1u) : "memory");
        if (prev == (unsigned)(NBLK2 - 1)) {
            float ne = 0.0f, ed = 0.0f;
            for (int i2 = 0; i2 < NBLK2; i2++) ne += __ldcg(&g_npart[i2]);
            for (int i2 = 0; i2 < NBLK2; i2++) ed += __ldcg(&g_epart[i2]);
            out_scal[0] = ne + ed;
            out_scal[1] = ne;
            out_scal[2] = ed;
        }
    }
}

// ---------------- launcher ---------------------------------------------------
extern "C" void kernel_launch(void* const* d_in, const int* in_sizes, int n_in,
                              void* d_out, int out_size) {
    const float* J     = (const float*)d_in[0];
    const float* bias  = (const float*)d_in[1];
    const float* gat_W = (const float*)d_in[2];
    const float* gat_a = (const float*)d_in[3];
    const float* W1    = (const float*)d_in[4];
    const float* b1    = (const float*)d_in[5];
    const float* W2    = (const float*)d_in[6];
    const float* b2    = (const float*)d_in[7];
    const float* W3    = (const float*)d_in[8];
    const float* b3    = (const float*)d_in[9];
    const int*   col   = (const int*)d_in[11];
    const int*   rev   = (const int*)d_in[12];
    const int*   ru    = (const int*)d_in[13];
    const int*   cu    = (const int*)d_in[14];
    const int*   u2e   = (const int*)d_in[15];

    int N  = in_sizes[1];
    int E  = in_sizes[10];
    int Eu = in_sizes[13];

    float* out = (float*)d_out;
    float* out_readout = out;                    // [N,2]
    float* out_pw      = out + 2 * N;            // [Eu,4]
    float* out_scal    = out + 2 * N + 4 * Eu;   // 3 scalars
    float* out_Ci      = out_scal + 3;           // [N]
    float* out_cij     = out_Ci + N;             // [Eu]
    float* out_dom     = out_cij + Eu;           // [N]

    k_feat<<<NBLK, NTHR>>>(J, bias, gat_W, gat_a, W1, b1, W2, b2, W3, b3,
                           col, N, E, out_Ci);
    k_bp<<<NBLK2, NTHR>>>(bias, col, rev, ru, cu, u2e, N, E, Eu,
                          out_readout, out_dom, out_pw, out_cij, out_scal);
}